// round 13
// baseline (speedup 1.0000x reference)
#include <cuda_runtime.h>
#include <cuda_fp16.h>
#include <cstdint>
#include <cstddef>

#define BATCH 4
#define NSEQ  4096
#define DHID  256
#define ROWS  16384            // BATCH * NSEQ

#define BM 128
#define BN 128
#define KC 32                  // K elements per pipeline chunk
#define TILE_BYTES 8192        // 128 rows * 32 fp16 * 2B
#define STAGEH_BYTES (2 * TILE_BYTES)
#define SMEMH_SZ (2 * STAGEH_BYTES)     // 32 KB (proj / scores pipeline)

// k_scores: mask tile with padded rows (132 ints = 528 B) to break bank conflicts
#define MROW_INTS 132
#define MASK_SMEM_OFF SMEMH_SZ
#define SMEMS_SZ (SMEMH_SZ + BM * MROW_INTS * 4)   // 32768 + 67584 = 100352

// k_pv: BM=64, full DHID=256. A 4KB + B 16KB per stage, 2 stages = 40 KB
#define PV_BM 64
#define PV_ABYTES 4096
#define PV_STAGE_BYTES (PV_ABYTES + 16384)
#define SMEMPV_SZ (2 * PV_STAGE_BYTES)  // 40960

// ---------------- device scratch (all fp16 single-plane) --------------------
__device__ __align__(16) __half g_Xf[(size_t)2 * ROWS * DHID];
__device__ __align__(16) __half g_Wtf[3 * DHID * DHID];
__device__ __align__(16) __half g_Qf[(size_t)ROWS * DHID];
__device__ __align__(16) __half g_Kf[(size_t)ROWS * DHID];
__device__ __align__(16) __half g_Vf[(size_t)BATCH * DHID * NSEQ];
__device__ __align__(16) __half g_Pf[(size_t)ROWS * NSEQ];
__device__ __align__(16) float  g_Lpart[(size_t)ROWS * 32];
__device__ __align__(16) float  g_Linv[(size_t)ROWS];

// ---------------- PTX helpers (arch-generic) --------------------------------
__device__ __forceinline__ uint32_t smem_u32(const void* p) {
    uint32_t a;
    asm("{ .reg .u64 t; cvta.to.shared.u64 t, %1; cvt.u32.u64 %0, t; }" : "=r"(a) : "l"(p));
    return a;
}
__device__ __forceinline__ uint32_t sw64(uint32_t b) { return b ^ ((b >> 3) & 0x30); }

__device__ __forceinline__ void cpa16(uint32_t dst, const void* src) {
    asm volatile("cp.async.cg.shared.global [%0], [%1], 16;" :: "r"(dst), "l"(src));
}
__device__ __forceinline__ void cp_commit() { asm volatile("cp.async.commit_group;"); }
template<int N> __device__ __forceinline__ void cp_wait() {
    asm volatile("cp.async.wait_group %0;" :: "n"(N));
}
__device__ __forceinline__ void ldm_x4(uint32_t* d, uint32_t a) {
    asm volatile("ldmatrix.sync.aligned.m8n8.x4.shared.b16 {%0,%1,%2,%3}, [%4];"
                 : "=r"(d[0]), "=r"(d[1]), "=r"(d[2]), "=r"(d[3]) : "r"(a));
}
__device__ __forceinline__ void ldm_x2(uint32_t* d, uint32_t a) {
    asm volatile("ldmatrix.sync.aligned.m8n8.x2.shared.b16 {%0,%1}, [%2];"
                 : "=r"(d[0]), "=r"(d[1]) : "r"(a));
}
__device__ __forceinline__ void mma16816h(float* d, const uint32_t* a, const uint32_t* b) {
    asm volatile("mma.sync.aligned.m16n8k16.row.col.f32.f16.f16.f32 "
                 "{%0,%1,%2,%3}, {%4,%5,%6,%7}, {%8,%9}, {%0,%1,%2,%3};"
                 : "+f"(d[0]), "+f"(d[1]), "+f"(d[2]), "+f"(d[3])
                 : "r"(a[0]), "r"(a[1]), "r"(a[2]), "r"(a[3]), "r"(b[0]), "r"(b[1]));
}

__device__ __forceinline__ uint32_t packh2(float a, float b) {
    __half2 h = __floats2half2_rn(a, b);
    return *(uint32_t*)&h;
}

// exp(x) on FMA pipe (MUFU shares MIO with LSU/ldmatrix: measured +25us there)
__device__ __forceinline__ float fast_exp(float x) {
    float t = x * 1.4426950408889634f;
    float n = floorf(t);
    float f = t - n;
    float p = 1.5404027e-4f;
    p = fmaf(p, f, 1.3333558e-3f);
    p = fmaf(p, f, 9.6181291e-3f);
    p = fmaf(p, f, 5.5504109e-2f);
    p = fmaf(p, f, 2.4022651e-1f);
    p = fmaf(p, f, 6.9314718e-1f);
    p = fmaf(p, f, 1.0f);
    int ni = (int)n;
    ni = max(ni, -126);
    return p * __int_as_float((ni + 127) << 23);
}

// ---------------- fp16 GEMM machinery (2-stage cp.async pipeline) -----------
__device__ __forceinline__ void prefetch_stage_h(const __half* A, const __half* B,
                                                 size_t ld, int c, int s,
                                                 uint32_t sbase, int tid) {
    size_t off = (size_t)(tid >> 1) * ld + (size_t)c * KC;
    int bo = (tid & 1) * 32;
    uint32_t rowb = (uint32_t)(tid >> 1) * 64 + bo;
    uint32_t stb = sbase + s * STAGEH_BYTES;
    const char* pa = (const char*)(A + off) + bo;
    const char* pb = (const char*)(B + off) + bo;
    #pragma unroll
    for (int j = 0; j < 2; ++j) {
        uint32_t d = sw64(rowb + j * 16);
        cpa16(stb + d,              pa + j * 16);
        cpa16(stb + TILE_BYTES + d, pb + j * 16);
    }
    cp_commit();
}

// A plane at stb, B plane at stb + ABYTES.
template<int ABYTES>
__device__ __forceinline__ void compute_stage_h(uint32_t stb, int wm, int wn, int lane,
                                                float acc[4][4][4]) {
    #pragma unroll
    for (int ks = 0; ks < 2; ++ks) {
        uint32_t a[4][4];
        int am  = (lane & 7) + ((lane >> 3) & 1) * 8;
        int akb = ks * 32 + (lane >> 4) * 16;
        #pragma unroll
        for (int mt = 0; mt < 4; ++mt) {
            uint32_t off = (uint32_t)(wm + mt * 16 + am) * 64 + akb;
            ldm_x4(a[mt], stb + sw64(off));
        }
        uint32_t b[4][2];
        int l16 = lane & 15;
        int bn  = l16 & 7;
        int bkb = ks * 32 + (l16 >> 3) * 16;
        #pragma unroll
        for (int nt = 0; nt < 4; ++nt) {
            uint32_t off = (uint32_t)(wn + nt * 8 + bn) * 64 + bkb;
            ldm_x2(b[nt], stb + ABYTES + sw64(off));
        }
        #pragma unroll
        for (int mt = 0; mt < 4; ++mt)
            #pragma unroll
            for (int nt = 0; nt < 4; ++nt)
                mma16816h(acc[mt][nt], a[mt], b[nt]);
    }
}

__device__ __forceinline__ void gemm_main_h(const __half* A, const __half* B, size_t ld,
                                            int nchunks, char* smem, float acc[4][4][4]) {
    int tid = threadIdx.x, lane = tid & 31, warp = tid >> 5;
    int wm = (warp >> 2) * 64, wn = (warp & 3) * 32;
    uint32_t sbase = smem_u32(smem);
    prefetch_stage_h(A, B, ld, 0, 0, sbase, tid);
    for (int c = 0; c < nchunks; ++c) {
        int s = c & 1;
        if (c + 1 < nchunks) { prefetch_stage_h(A, B, ld, c + 1, s ^ 1, sbase, tid); cp_wait<1>(); }
        else                 { cp_wait<0>(); }
        __syncthreads();
        compute_stage_h<TILE_BYTES>(sbase + s * STAGEH_BYTES, wm, wn, lane, acc);
        __syncthreads();
    }
}

// ---------------- prep kernels ---------------------------------------------
__global__ __launch_bounds__(256)
void k_prep_x(const float* __restrict__ x1, const float* __restrict__ x2) {
    size_t i = ((size_t)blockIdx.x * 256 + threadIdx.x) * 4;
    const size_t half = (size_t)ROWS * DHID;
    const float* src = (i < half) ? (x1 + i) : (x2 + (i - half));
    float4 v = *(const float4*)src;
    *(uint2*)(g_Xf + i) = make_uint2(packh2(v.x, v.y), packh2(v.z, v.w));
}

__global__ void k_prep_w(const float* __restrict__ Wq, const float* __restrict__ Wk,
                         const float* __restrict__ Wv) {
    __shared__ float t[32][33];
    int z = blockIdx.z;
    const float* W = (z == 0) ? Wq : ((z == 1) ? Wk : Wv);
    int n0 = blockIdx.x * 32, d0 = blockIdx.y * 32;
    int tx = threadIdx.x, ty = threadIdx.y;           // block (32,8)
    #pragma unroll
    for (int i = 0; i < 4; ++i)
        t[ty + i * 8][tx] = W[(size_t)(d0 + ty + i * 8) * DHID + n0 + tx];
    __syncthreads();
    #pragma unroll
    for (int i = 0; i < 4; ++i) {
        float f = t[tx][ty + i * 8];
        size_t o = (size_t)z * DHID * DHID + (size_t)(n0 + ty + i * 8) * DHID + d0 + tx;
        g_Wtf[o] = __float2half(f);
    }
}

// ---------------- projection (fp16 in, fp16 out) ----------------------------
__global__ __launch_bounds__(256, 2)
void k_proj(const float* __restrict__ bq, const float* __restrict__ bk,
            const float* __restrict__ bv) {
    extern __shared__ char smem[];
    int z = blockIdx.z;
    int rowBase = blockIdx.y * BM, colBase = blockIdx.x * BN;
    const __half* A = g_Xf + (((z == 0) ? 0 : (size_t)ROWS) + rowBase) * DHID;
    const __half* B = g_Wtf + (size_t)z * DHID * DHID + (size_t)colBase * DHID;

    float acc[4][4][4];
    #pragma unroll
    for (int a = 0; a < 4; ++a)
        #pragma unroll
        for (int b = 0; b < 4; ++b)
            #pragma unroll
            for (int c = 0; c < 4; ++c) acc[a][b][c] = 0.f;

    gemm_main_h(A, B, DHID, DHID / KC, smem, acc);

    const float* bias = (z == 0) ? bq : ((z == 1) ? bk : bv);
    int lane = threadIdx.x & 31, warp = threadIdx.x >> 5;
    int wm = (warp >> 2) * 64, wn = (warp & 3) * 32;
    int rl = lane >> 2, cl = (lane & 3) * 2;
    #pragma unroll
    for (int mt = 0; mt < 4; ++mt)
        #pragma unroll
        for (int nt = 0; nt < 4; ++nt) {
            int col = colBase + wn + nt * 8 + cl;
            float b0 = bias[col], b1 = bias[col + 1];
            #pragma unroll
            for (int h = 0; h < 2; ++h) {
                int r = rowBase + wm + mt * 16 + rl + h * 8;
                float v0 = acc[mt][nt][h * 2 + 0] + b0;
                float v1 = acc[mt][nt][h * 2 + 1] + b1;
                if (z < 2) {
                    __half* d = (z == 0) ? g_Qf : g_Kf;
                    *(uint32_t*)&d[(size_t)r * DHID + col] = packh2(v0, v1);
                } else {
                    int bb = r >> 12, j = r & 4095;
                    size_t o0 = ((size_t)(bb * DHID + col)) * NSEQ + j;
                    g_Vf[o0]        = __float2half(v0);
                    g_Vf[o0 + NSEQ] = __float2half(v1);
                }
            }
        }
}

// ---------------- scores + masked exp -> P (fp16); mask staged (padded) -----
__global__ __launch_bounds__(256, 2)
void k_scores(const int* __restrict__ mask) {
    extern __shared__ char smem[];
    int bz = blockIdx.z;
    int rowBase = blockIdx.y * BM, colBase = blockIdx.x * BN;
    const __half* A = g_Qf + ((size_t)bz * NSEQ + rowBase) * DHID;
    const __half* B = g_Kf + ((size_t)bz * NSEQ + colBase) * DHID;
    int tid = threadIdx.x;
    uint32_t sbase = smem_u32(smem);

    // prefetch mask tile (128 rows x 128 ints) into smem with 528B row stride
    {
        const char* msrc = (const char*)(mask
            + ((size_t)bz * NSEQ + rowBase) * NSEQ + colBase);
        uint32_t mdst = sbase + MASK_SMEM_OFF;
        #pragma unroll
        for (int i = 0; i < 16; ++i) {
            int idx = tid + i * 256;          // 16B chunk id, 0..4095
            int row = idx >> 5, seg = idx & 31;
            cpa16(mdst + (uint32_t)(row * (MROW_INTS * 4) + seg * 16),
                  msrc + (size_t)row * NSEQ * 4 + seg * 16);
        }
        cp_commit();
    }

    float acc[4][4][4];
    #pragma unroll
    for (int a = 0; a < 4; ++a)
        #pragma unroll
        for (int b = 0; b < 4; ++b)
            #pragma unroll
            for (int c = 0; c < 4; ++c) acc[a][b][c] = 0.f;

    gemm_main_h(A, B, DHID, DHID / KC, smem, acc);
    // final cp_wait<0> + syncthreads in gemm_main_h guarantees mask residency

    int lane = tid & 31, warp = tid >> 5;
    int wm = (warp >> 2) * 64, wn = (warp & 3) * 32;
    int rl = lane >> 2, cl = (lane & 3) * 2;
    const float scale = 0.0625f;
    const int* msm = (const int*)(smem + MASK_SMEM_OFF);

    float rs[4][2];
    #pragma unroll
    for (int mt = 0; mt < 4; ++mt) { rs[mt][0] = 0.f; rs[mt][1] = 0.f; }

    #pragma unroll
    for (int mt = 0; mt < 4; ++mt)
        #pragma unroll
        for (int h = 0; h < 2; ++h) {
            int rL = wm + mt * 16 + rl + h * 8;
            const int* mrow = msm + rL * MROW_INTS + wn + cl;
            __half* prow = g_Pf + ((size_t)bz * NSEQ + rowBase + rL) * NSEQ
                         + colBase + wn + cl;
            #pragma unroll
            for (int nt = 0; nt < 4; ++nt) {
                int2 mk = *(const int2*)(mrow + nt * 8);
                float e0 = (mk.x > 0) ? fast_exp(acc[mt][nt][h * 2 + 0] * scale) : 1.0f;
                float e1 = (mk.y > 0) ? fast_exp(acc[mt][nt][h * 2 + 1] * scale) : 1.0f;
                rs[mt][h] += e0 + e1;
                *(uint32_t*)(prow + nt * 8) = packh2(e0, e1);
            }
        }

    // reduce row sums: lanes sharing a row differ in (lane & 3)
    float* sRed = (float*)smem;                 // [128][4]
    __syncthreads();
    #pragma unroll
    for (int mt = 0; mt < 4; ++mt)
        #pragma unroll
        for (int h = 0; h < 2; ++h) {
            float v = rs[mt][h];
            v += __shfl_xor_sync(~0u, v, 1);
            v += __shfl_xor_sync(~0u, v, 2);
            if ((lane & 3) == 0) {
                int lr = wm + mt * 16 + rl + h * 8;
                sRed[lr * 4 + (warp & 3)] = v;
            }
        }
    __syncthreads();
    if (tid < 128) {
        float s = sRed[tid * 4] + sRed[tid * 4 + 1] + sRed[tid * 4 + 2] + sRed[tid * 4 + 3];
        g_Lpart[((size_t)bz * NSEQ + rowBase + tid) * 32 + blockIdx.x] = s;
    }
}

__global__ __launch_bounds__(256)
void k_sumL() {
    int row = blockIdx.x * 256 + threadIdx.x;
    const float4* p = (const float4*)(g_Lpart + (size_t)row * 32);
    float s = 0.f;
    #pragma unroll
    for (int i = 0; i < 8; ++i) {
        float4 v = p[i];
        s += (v.x + v.y) + (v.z + v.w);
    }
    g_Linv[row] = 1.0f / s;
}

// ---------------- PV: BM=64 x DHID=256, 256 threads, 2 CTA/SM ---------------
// P read exactly once. A tile 64x32 (4KB) + B tile 256x32 (16KB) per stage.
__device__ __forceinline__ void prefetch_pv(const __half* A, const __half* B,
                                            int c, int s, uint32_t sbase, int tid) {
    uint32_t stb = sbase + s * PV_STAGE_BYTES;
    // A: 64 rows x 4 chunks = 256 chunks of 16B, one per thread
    {
        int row = tid >> 2, seg = tid & 3;
        uint32_t d = sw64((uint32_t)row * 64 + seg * 16);
        cpa16(stb + d, (const char*)(A + (size_t)row * NSEQ + (size_t)c * KC) + seg * 16);
    }
    // B: 256 rows x 4 chunks = 1024 chunks of 16B, 4 per thread
    #pragma unroll
    for (int i = 0; i < 4; ++i) {
        int cidx = tid + i * 256;
        int row = cidx >> 2, seg = cidx & 3;
        uint32_t d = sw64((uint32_t)row * 64 + seg * 16);
        cpa16(stb + PV_ABYTES + d,
              (const char*)(B + (size_t)row * NSEQ + (size_t)c * KC) + seg * 16);
    }
    cp_commit();
}

__global__ __launch_bounds__(256, 2)
void k_pv(float* __restrict__ out) {
    extern __shared__ char smem[];
    int bz = blockIdx.z;
    int rowBase = blockIdx.y * PV_BM;
    const __half* A = g_Pf + ((size_t)bz * NSEQ + rowBase) * NSEQ;
    const __half* B = g_Vf + (size_t)bz * DHID * NSEQ;

    float acc[4][4][4];
    #pragma unroll
    for (int a = 0; a < 4; ++a)
        #pragma unroll
        for (int b = 0; b < 4; ++b)
            #pragma unroll
            for (int c = 0; c < 4; ++c) acc[a][b][c] = 0.f;

    int tid = threadIdx.x, lane = tid & 31, warp = tid >> 5;
    // 8 warps: 1 (M) x 8 (N); warp tile 64x32
    int wm = 0, wn = warp * 32;
    uint32_t sbase = smem_u32(smem);
    prefetch_pv(A, B, 0, 0, sbase, tid);
    const int nchunks = NSEQ / KC;
    for (int c = 0; c < nchunks; ++c) {
        int s = c & 1;
        if (c + 1 < nchunks) { prefetch_pv(A, B, c + 1, s ^ 1, sbase, tid); cp_wait<1>(); }
        else                 { cp_wait<0>(); }
        __syncthreads();
        compute_stage_h<PV_ABYTES>(sbase + s * PV_STAGE_BYTES, wm, wn, lane, acc);
        __syncthreads();
    }

    int rl = lane >> 2, cl = (lane & 3) * 2;
    float linv[4][2];
    #pragma unroll
    for (int mt = 0; mt < 4; ++mt)
        #pragma unroll
        for (int h = 0; h < 2; ++h) {
            int r = rowBase + mt * 16 + rl + h * 8;
            linv[mt][h] = g_Linv[(size_t)bz * NSEQ + r];
        }

    #pragma unroll
    for (int mt = 0; mt < 4; ++mt)
        #pragma unroll
        for (int nt = 0; nt < 4; ++nt) {
            int col = wn + nt * 8 + cl;
            #pragma unroll
            for (int h = 0; h < 2; ++h) {
                int r = rowBase + mt * 16 + rl + h * 8;
                float2 o;
                o.x = acc[mt][nt][h * 2 + 0] * linv[mt][h];
                o.y = acc[mt][nt][h * 2 + 1] * linv[mt][h];
                *(float2*)&out[((size_t)bz * NSEQ + r) * DHID + col] = o;
            }
        }
}

// ---------------------------------------------------------------------------
extern "C" void kernel_launch(void* const* d_in, const int* in_sizes, int n_in,
                              void* d_out, int out_size) {
    const float* x1  = (const float*)d_in[0];
    const float* x2  = (const float*)d_in[1];
    const int*   msk = (const int*)  d_in[2];
    const float* Wq  = (const float*)d_in[3];
    const float* bq  = (const float*)d_in[4];
    const float* Wk  = (const float*)d_in[5];
    const float* bk  = (const float*)d_in[6];
    const float* Wv  = (const float*)d_in[7];
    const float* bv  = (const float*)d_in[8];
    float* out = (float*)d_out;

    cudaFuncSetAttribute(k_proj,   cudaFuncAttributeMaxDynamicSharedMemorySize, SMEMH_SZ);
    cudaFuncSetAttribute(k_scores, cudaFuncAttributeMaxDynamicSharedMemorySize, SMEMS_SZ);
    cudaFuncSetAttribute(k_pv,     cudaFuncAttributeMaxDynamicSharedMemorySize, SMEMPV_SZ);

    k_prep_x <<<8192, 256>>>(x1, x2);
    k_prep_w <<<dim3(8, 8, 3), dim3(32, 8)>>>(Wq, Wk, Wv);
    k_proj   <<<dim3(2, 128, 3), 256, SMEMH_SZ>>>(bq, bk, bv);
    k_scores <<<dim3(32, 32, 4), 256, SMEMS_SZ>>>(msk);
    k_sumL   <<<ROWS / 256, 256>>>();
    k_pv     <<<dim3(1, 64, 4), 256, SMEMPV_SZ>>>(out);
}

// round 14
// speedup vs baseline: 1.0511x; 1.0511x over previous
#include <cuda_runtime.h>
#include <cuda_fp16.h>
#include <cstdint>
#include <cstddef>

#define BATCH 4
#define NSEQ  4096
#define DHID  256
#define ROWS  16384            // BATCH * NSEQ

#define BM 128
#define BN 128
#define KC 32                  // K elements per pipeline chunk
#define TILE_BYTES 8192        // 128 rows * 32 fp16 * 2B
#define STAGEH_BYTES (2 * TILE_BYTES)
#define SMEMH_SZ (2 * STAGEH_BYTES)     // 32 KB (proj pipeline)

// k_scores: BM=128 x BN=64 tile, 3 CTAs/SM.
// pipeline: A 8KB + B 4KB per stage, 2 stages = 24 KB; mask tile 128x68 ints.
#define S_BN 64
#define S_ABYTES 8192
#define S_STAGE (S_ABYTES + 4096)        // 12288
#define MASK_SMEM_OFF (2 * S_STAGE)      // 24576
#define MROW_INTS 68                     // 272 B row stride (16B aligned, bank-shifted)
#define SMEMS_SZ (MASK_SMEM_OFF + BM * MROW_INTS * 4)   // 24576 + 34816 = 59392
#define NCOLB (NSEQ / S_BN)              // 64 column blocks

// k_pv (512-thread, full-DHID) tiling — R12 proven config
#define PV_STAGE_BYTES 24576             // A 8KB + B 16KB
#define SMEMPV_SZ (2 * PV_STAGE_BYTES)   // 48 KB

// ---------------- device scratch (all fp16 single-plane) --------------------
__device__ __align__(16) __half g_Xf[(size_t)2 * ROWS * DHID];
__device__ __align__(16) __half g_Wtf[3 * DHID * DHID];
__device__ __align__(16) __half g_Qf[(size_t)ROWS * DHID];
__device__ __align__(16) __half g_Kf[(size_t)ROWS * DHID];
__device__ __align__(16) __half g_Vf[(size_t)BATCH * DHID * NSEQ];
__device__ __align__(16) __half g_Pf[(size_t)ROWS * NSEQ];
__device__ __align__(16) float  g_Lpart[(size_t)ROWS * NCOLB];
__device__ __align__(16) float  g_Linv[(size_t)ROWS];

// ---------------- PTX helpers (arch-generic) --------------------------------
__device__ __forceinline__ uint32_t smem_u32(const void* p) {
    uint32_t a;
    asm("{ .reg .u64 t; cvta.to.shared.u64 t, %1; cvt.u32.u64 %0, t; }" : "=r"(a) : "l"(p));
    return a;
}
__device__ __forceinline__ uint32_t sw64(uint32_t b) { return b ^ ((b >> 3) & 0x30); }

__device__ __forceinline__ void cpa16(uint32_t dst, const void* src) {
    asm volatile("cp.async.cg.shared.global [%0], [%1], 16;" :: "r"(dst), "l"(src));
}
__device__ __forceinline__ void cp_commit() { asm volatile("cp.async.commit_group;"); }
template<int N> __device__ __forceinline__ void cp_wait() {
    asm volatile("cp.async.wait_group %0;" :: "n"(N));
}
__device__ __forceinline__ void ldm_x4(uint32_t* d, uint32_t a) {
    asm volatile("ldmatrix.sync.aligned.m8n8.x4.shared.b16 {%0,%1,%2,%3}, [%4];"
                 : "=r"(d[0]), "=r"(d[1]), "=r"(d[2]), "=r"(d[3]) : "r"(a));
}
__device__ __forceinline__ void ldm_x2(uint32_t* d, uint32_t a) {
    asm volatile("ldmatrix.sync.aligned.m8n8.x2.shared.b16 {%0,%1}, [%2];"
                 : "=r"(d[0]), "=r"(d[1]) : "r"(a));
}
__device__ __forceinline__ void mma16816h(float* d, const uint32_t* a, const uint32_t* b) {
    asm volatile("mma.sync.aligned.m16n8k16.row.col.f32.f16.f16.f32 "
                 "{%0,%1,%2,%3}, {%4,%5,%6,%7}, {%8,%9}, {%0,%1,%2,%3};"
                 : "+f"(d[0]), "+f"(d[1]), "+f"(d[2]), "+f"(d[3])
                 : "r"(a[0]), "r"(a[1]), "r"(a[2]), "r"(a[3]), "r"(b[0]), "r"(b[1]));
}

__device__ __forceinline__ uint32_t packh2(float a, float b) {
    __half2 h = __floats2half2_rn(a, b);
    return *(uint32_t*)&h;
}

// exp(x) on FMA pipe (MUFU shares MIO with LSU/ldmatrix: measured +25us there)
__device__ __forceinline__ float fast_exp(float x) {
    float t = x * 1.4426950408889634f;
    float n = floorf(t);
    float f = t - n;
    float p = 1.5404027e-4f;
    p = fmaf(p, f, 1.3333558e-3f);
    p = fmaf(p, f, 9.6181291e-3f);
    p = fmaf(p, f, 5.5504109e-2f);
    p = fmaf(p, f, 2.4022651e-1f);
    p = fmaf(p, f, 6.9314718e-1f);
    p = fmaf(p, f, 1.0f);
    int ni = (int)n;
    ni = max(ni, -126);
    return p * __int_as_float((ni + 127) << 23);
}

// ---------------- fp16 GEMM machinery, 64x32 warp tile (proj / pv) ----------
__device__ __forceinline__ void prefetch_stage_h(const __half* A, const __half* B,
                                                 size_t ld, int c, int s,
                                                 uint32_t sbase, int tid) {
    size_t off = (size_t)(tid >> 1) * ld + (size_t)c * KC;
    int bo = (tid & 1) * 32;
    uint32_t rowb = (uint32_t)(tid >> 1) * 64 + bo;
    uint32_t stb = sbase + s * STAGEH_BYTES;
    const char* pa = (const char*)(A + off) + bo;
    const char* pb = (const char*)(B + off) + bo;
    #pragma unroll
    for (int j = 0; j < 2; ++j) {
        uint32_t d = sw64(rowb + j * 16);
        cpa16(stb + d,              pa + j * 16);
        cpa16(stb + TILE_BYTES + d, pb + j * 16);
    }
    cp_commit();
}

template<int ABYTES>
__device__ __forceinline__ void compute_stage_h(uint32_t stb, int wm, int wn, int lane,
                                                float acc[4][4][4]) {
    #pragma unroll
    for (int ks = 0; ks < 2; ++ks) {
        uint32_t a[4][4];
        int am  = (lane & 7) + ((lane >> 3) & 1) * 8;
        int akb = ks * 32 + (lane >> 4) * 16;
        #pragma unroll
        for (int mt = 0; mt < 4; ++mt) {
            uint32_t off = (uint32_t)(wm + mt * 16 + am) * 64 + akb;
            ldm_x4(a[mt], stb + sw64(off));
        }
        uint32_t b[4][2];
        int l16 = lane & 15;
        int bn  = l16 & 7;
        int bkb = ks * 32 + (l16 >> 3) * 16;
        #pragma unroll
        for (int nt = 0; nt < 4; ++nt) {
            uint32_t off = (uint32_t)(wn + nt * 8 + bn) * 64 + bkb;
            ldm_x2(b[nt], stb + ABYTES + sw64(off));
        }
        #pragma unroll
        for (int mt = 0; mt < 4; ++mt)
            #pragma unroll
            for (int nt = 0; nt < 4; ++nt)
                mma16816h(acc[mt][nt], a[mt], b[nt]);
    }
}

__device__ __forceinline__ void gemm_main_h(const __half* A, const __half* B, size_t ld,
                                            int nchunks, char* smem, float acc[4][4][4]) {
    int tid = threadIdx.x, lane = tid & 31, warp = tid >> 5;
    int wm = (warp >> 2) * 64, wn = (warp & 3) * 32;
    uint32_t sbase = smem_u32(smem);
    prefetch_stage_h(A, B, ld, 0, 0, sbase, tid);
    for (int c = 0; c < nchunks; ++c) {
        int s = c & 1;
        if (c + 1 < nchunks) { prefetch_stage_h(A, B, ld, c + 1, s ^ 1, sbase, tid); cp_wait<1>(); }
        else                 { cp_wait<0>(); }
        __syncthreads();
        compute_stage_h<TILE_BYTES>(sbase + s * STAGEH_BYTES, wm, wn, lane, acc);
        __syncthreads();
    }
}

// ---------------- prep kernels ---------------------------------------------
__global__ __launch_bounds__(256)
void k_prep_x(const float* __restrict__ x1, const float* __restrict__ x2) {
    size_t i = ((size_t)blockIdx.x * 256 + threadIdx.x) * 4;
    const size_t half = (size_t)ROWS * DHID;
    const float* src = (i < half) ? (x1 + i) : (x2 + (i - half));
    float4 v = *(const float4*)src;
    *(uint2*)(g_Xf + i) = make_uint2(packh2(v.x, v.y), packh2(v.z, v.w));
}

__global__ void k_prep_w(const float* __restrict__ Wq, const float* __restrict__ Wk,
                         const float* __restrict__ Wv) {
    __shared__ float t[32][33];
    int z = blockIdx.z;
    const float* W = (z == 0) ? Wq : ((z == 1) ? Wk : Wv);
    int n0 = blockIdx.x * 32, d0 = blockIdx.y * 32;
    int tx = threadIdx.x, ty = threadIdx.y;           // block (32,8)
    #pragma unroll
    for (int i = 0; i < 4; ++i)
        t[ty + i * 8][tx] = W[(size_t)(d0 + ty + i * 8) * DHID + n0 + tx];
    __syncthreads();
    #pragma unroll
    for (int i = 0; i < 4; ++i) {
        float f = t[tx][ty + i * 8];
        size_t o = (size_t)z * DHID * DHID + (size_t)(n0 + ty + i * 8) * DHID + d0 + tx;
        g_Wtf[o] = __float2half(f);
    }
}

// ---------------- projection (fp16 in, fp16 out) ----------------------------
__global__ __launch_bounds__(256, 2)
void k_proj(const float* __restrict__ bq, const float* __restrict__ bk,
            const float* __restrict__ bv) {
    extern __shared__ char smem[];
    int z = blockIdx.z;
    int rowBase = blockIdx.y * BM, colBase = blockIdx.x * BN;
    const __half* A = g_Xf + (((z == 0) ? 0 : (size_t)ROWS) + rowBase) * DHID;
    const __half* B = g_Wtf + (size_t)z * DHID * DHID + (size_t)colBase * DHID;

    float acc[4][4][4];
    #pragma unroll
    for (int a = 0; a < 4; ++a)
        #pragma unroll
        for (int b = 0; b < 4; ++b)
            #pragma unroll
            for (int c = 0; c < 4; ++c) acc[a][b][c] = 0.f;

    gemm_main_h(A, B, DHID, DHID / KC, smem, acc);

    const float* bias = (z == 0) ? bq : ((z == 1) ? bk : bv);
    int lane = threadIdx.x & 31, warp = threadIdx.x >> 5;
    int wm = (warp >> 2) * 64, wn = (warp & 3) * 32;
    int rl = lane >> 2, cl = (lane & 3) * 2;
    #pragma unroll
    for (int mt = 0; mt < 4; ++mt)
        #pragma unroll
        for (int nt = 0; nt < 4; ++nt) {
            int col = colBase + wn + nt * 8 + cl;
            float b0 = bias[col], b1 = bias[col + 1];
            #pragma unroll
            for (int h = 0; h < 2; ++h) {
                int r = rowBase + wm + mt * 16 + rl + h * 8;
                float v0 = acc[mt][nt][h * 2 + 0] + b0;
                float v1 = acc[mt][nt][h * 2 + 1] + b1;
                if (z < 2) {
                    __half* d = (z == 0) ? g_Qf : g_Kf;
                    *(uint32_t*)&d[(size_t)r * DHID + col] = packh2(v0, v1);
                } else {
                    int bb = r >> 12, j = r & 4095;
                    size_t o0 = ((size_t)(bb * DHID + col)) * NSEQ + j;
                    g_Vf[o0]        = __float2half(v0);
                    g_Vf[o0 + NSEQ] = __float2half(v1);
                }
            }
        }
}

// ---------------- scores: BM=128 x BN=64, warp tile 32x32, 3 CTA/SM ---------
__device__ __forceinline__ void prefetch_s(const __half* A, const __half* B,
                                           int c, int s, uint32_t sbase, int tid) {
    uint32_t stb = sbase + s * S_STAGE;
    // A: 128 rows x 4 chunks = 512 chunks of 16B
    #pragma unroll
    for (int i = 0; i < 2; ++i) {
        int idx = tid + i * 256;
        int row = idx >> 2, seg = idx & 3;
        uint32_t d = sw64((uint32_t)row * 64 + seg * 16);
        cpa16(stb + d, (const char*)(A + (size_t)row * DHID + (size_t)c * KC) + seg * 16);
    }
    // B: 64 rows x 4 chunks = 256 chunks of 16B
    {
        int row = tid >> 2, seg = tid & 3;
        uint32_t d = sw64((uint32_t)row * 64 + seg * 16);
        cpa16(stb + S_ABYTES + d,
              (const char*)(B + (size_t)row * DHID + (size_t)c * KC) + seg * 16);
    }
    cp_commit();
}

__device__ __forceinline__ void compute_s(uint32_t stb, int wm, int wn, int lane,
                                          float acc[2][4][4]) {
    #pragma unroll
    for (int ks = 0; ks < 2; ++ks) {
        uint32_t a[2][4];
        int am  = (lane & 7) + ((lane >> 3) & 1) * 8;
        int akb = ks * 32 + (lane >> 4) * 16;
        #pragma unroll
        for (int mt = 0; mt < 2; ++mt) {
            uint32_t off = (uint32_t)(wm + mt * 16 + am) * 64 + akb;
            ldm_x4(a[mt], stb + sw64(off));
        }
        uint32_t b[4][2];
        int l16 = lane & 15;
        int bn  = l16 & 7;
        int bkb = ks * 32 + (l16 >> 3) * 16;
        #pragma unroll
        for (int nt = 0; nt < 4; ++nt) {
            uint32_t off = (uint32_t)(wn + nt * 8 + bn) * 64 + bkb;
            ldm_x2(b[nt], stb + S_ABYTES + sw64(off));
        }
        #pragma unroll
        for (int mt = 0; mt < 2; ++mt)
            #pragma unroll
            for (int nt = 0; nt < 4; ++nt)
                mma16816h(acc[mt][nt], a[mt], b[nt]);
    }
}

__global__ __launch_bounds__(256, 3)
void k_scores(const int* __restrict__ mask) {
    extern __shared__ char smem[];
    int bz = blockIdx.z;
    int rowBase = blockIdx.y * BM, colBase = blockIdx.x * S_BN;
    const __half* A = g_Qf + ((size_t)bz * NSEQ + rowBase) * DHID;
    const __half* B = g_Kf + ((size_t)bz * NSEQ + colBase) * DHID;
    int tid = threadIdx.x;
    uint32_t sbase = smem_u32(smem);

    // mask tile prefetch: 128 rows x 64 ints, smem row stride 272 B
    {
        const char* msrc = (const char*)(mask
            + ((size_t)bz * NSEQ + rowBase) * NSEQ + colBase);
        uint32_t mdst = sbase + MASK_SMEM_OFF;
        #pragma unroll
        for (int i = 0; i < 8; ++i) {
            int idx = tid + i * 256;          // 16B chunk id, 0..2047
            int row = idx >> 4, seg = idx & 15;
            cpa16(mdst + (uint32_t)(row * (MROW_INTS * 4) + seg * 16),
                  msrc + (size_t)row * NSEQ * 4 + seg * 16);
        }
        cp_commit();
    }

    float acc[2][4][4];
    #pragma unroll
    for (int a = 0; a < 2; ++a)
        #pragma unroll
        for (int b = 0; b < 4; ++b)
            #pragma unroll
            for (int c = 0; c < 4; ++c) acc[a][b][c] = 0.f;

    int lane = tid & 31, warp = tid >> 5;
    int wm = (warp >> 1) * 32, wn = (warp & 1) * 32;
    prefetch_s(A, B, 0, 0, sbase, tid);
    const int nchunks = DHID / KC;        // 8
    for (int c = 0; c < nchunks; ++c) {
        int s = c & 1;
        if (c + 1 < nchunks) { prefetch_s(A, B, c + 1, s ^ 1, sbase, tid); cp_wait<1>(); }
        else                 { cp_wait<0>(); }
        __syncthreads();
        compute_s(sbase + s * S_STAGE, wm, wn, lane, acc);
        __syncthreads();
    }

    int rl = lane >> 2, cl = (lane & 3) * 2;
    const float scale = 0.0625f;
    const int* msm = (const int*)(smem + MASK_SMEM_OFF);

    float rs[2][2];
    rs[0][0] = rs[0][1] = rs[1][0] = rs[1][1] = 0.f;

    #pragma unroll
    for (int mt = 0; mt < 2; ++mt)
        #pragma unroll
        for (int h = 0; h < 2; ++h) {
            int rL = wm + mt * 16 + rl + h * 8;
            const int* mrow = msm + rL * MROW_INTS + wn + cl;
            __half* prow = g_Pf + ((size_t)bz * NSEQ + rowBase + rL) * NSEQ
                         + colBase + wn + cl;
            #pragma unroll
            for (int nt = 0; nt < 4; ++nt) {
                int2 mk = *(const int2*)(mrow + nt * 8);
                float e0 = (mk.x > 0) ? fast_exp(acc[mt][nt][h * 2 + 0] * scale) : 1.0f;
                float e1 = (mk.y > 0) ? fast_exp(acc[mt][nt][h * 2 + 1] * scale) : 1.0f;
                rs[mt][h] += e0 + e1;
                *(uint32_t*)(prow + nt * 8) = packh2(e0, e1);
            }
        }

    // row-sum reduce: quad lanes (shfl), then the 2 warps sharing each row (smem)
    float* sRed = (float*)smem;                 // [128][2]
    __syncthreads();
    #pragma unroll
    for (int mt = 0; mt < 2; ++mt)
        #pragma unroll
        for (int h = 0; h < 2; ++h) {
            float v = rs[mt][h];
            v += __shfl_xor_sync(~0u, v, 1);
            v += __shfl_xor_sync(~0u, v, 2);
            if ((lane & 3) == 0) {
                int lr = wm + mt * 16 + rl + h * 8;
                sRed[lr * 2 + (warp & 1)] = v;
            }
        }
    __syncthreads();
    if (tid < 128) {
        float s = sRed[tid * 2] + sRed[tid * 2 + 1];
        g_Lpart[((size_t)bz * NSEQ + rowBase + tid) * NCOLB + blockIdx.x] = s;
    }
}

__global__ __launch_bounds__(256)
void k_sumL() {
    int row = blockIdx.x * 256 + threadIdx.x;
    const float4* p = (const float4*)(g_Lpart + (size_t)row * NCOLB);
    float s = 0.f;
    #pragma unroll
    for (int i = 0; i < NCOLB / 4; ++i) {
        float4 v = p[i];
        s += (v.x + v.y) + (v.z + v.w);
    }
    g_Linv[row] = 1.0f / s;
}

// ---------------- PV: 512 threads, BM=128 x full DHID=256 (R12 config) ------
__device__ __forceinline__ void prefetch_pv(const __half* A, const __half* B,
                                            int c, int s, uint32_t sbase, int tid) {
    uint32_t stb = sbase + s * PV_STAGE_BYTES;
    // A: 512 chunks of 16B
    {
        int row = tid >> 2, seg = tid & 3;
        uint32_t d = sw64((uint32_t)row * 64 + seg * 16);
        cpa16(stb + d, (const char*)(A + (size_t)row * NSEQ + (size_t)c * KC) + seg * 16);
    }
    // B: 1024 chunks of 16B
    #pragma unroll
    for (int i = 0; i < 2; ++i) {
        int cidx = tid + i * 512;
        int row = cidx >> 2, seg = cidx & 3;
        uint32_t d = sw64((uint32_t)row * 64 + seg * 16);
        cpa16(stb + TILE_BYTES + d,
              (const char*)(B + (size_t)row * NSEQ + (size_t)c * KC) + seg * 16);
    }
    cp_commit();
}

__global__ __launch_bounds__(512, 1)
void k_pv(float* __restrict__ out) {
    extern __shared__ char smem[];
    int bz = blockIdx.z;
    int rowBase = blockIdx.y * BM;
    const __half* A = g_Pf + ((size_t)bz * NSEQ + rowBase) * NSEQ;
    const __half* B = g_Vf + (size_t)bz * DHID * NSEQ;

    float acc[4][4][4];
    #pragma unroll
    for (int a = 0; a < 4; ++a)
        #pragma unroll
        for (int b = 0; b < 4; ++b)
            #pragma unroll
            for (int c = 0; c < 4; ++c) acc[a][b][c] = 0.f;

    int tid = threadIdx.x, lane = tid & 31, warp = tid >> 5;
    // 16 warps: 2 (M) x 8 (N)
    int wm = (warp >> 3) * 64, wn = (warp & 7) * 32;
    uint32_t sbase = smem_u32(smem);
    prefetch_pv(A, B, 0, 0, sbase, tid);
    const int nchunks = NSEQ / KC;
    for (int c = 0; c < nchunks; ++c) {
        int s = c & 1;
        if (c + 1 < nchunks) { prefetch_pv(A, B, c + 1, s ^ 1, sbase, tid); cp_wait<1>(); }
        else                 { cp_wait<0>(); }
        __syncthreads();
        compute_stage_h<TILE_BYTES>(sbase + s * PV_STAGE_BYTES, wm, wn, lane, acc);
        __syncthreads();
    }

    int rl = lane >> 2, cl = (lane & 3) * 2;
    float linv[4][2];
    #pragma unroll
    for (int mt = 0; mt < 4; ++mt)
        #pragma unroll
        for (int h = 0; h < 2; ++h) {
            int r = rowBase + wm + mt * 16 + rl + h * 8;
            linv[mt][h] = g_Linv[(size_t)bz * NSEQ + r];
        }

    #pragma unroll
    for (int mt = 0; mt < 4; ++mt)
        #pragma unroll
        for (int nt = 0; nt < 4; ++nt) {
            int col = wn + nt * 8 + cl;
            #pragma unroll
            for (int h = 0; h < 2; ++h) {
                int r = rowBase + wm + mt * 16 + rl + h * 8;
                float2 o;
                o.x = acc[mt][nt][h * 2 + 0] * linv[mt][h];
                o.y = acc[mt][nt][h * 2 + 1] * linv[mt][h];
                *(float2*)&out[((size_t)bz * NSEQ + r) * DHID + col] = o;
            }
        }
}

// ---------------------------------------------------------------------------
extern "C" void kernel_launch(void* const* d_in, const int* in_sizes, int n_in,
                              void* d_out, int out_size) {
    const float* x1  = (const float*)d_in[0];
    const float* x2  = (const float*)d_in[1];
    const int*   msk = (const int*)  d_in[2];
    const float* Wq  = (const float*)d_in[3];
    const float* bq  = (const float*)d_in[4];
    const float* Wk  = (const float*)d_in[5];
    const float* bk  = (const float*)d_in[6];
    const float* Wv  = (const float*)d_in[7];
    const float* bv  = (const float*)d_in[8];
    float* out = (float*)d_out;

    cudaFuncSetAttribute(k_proj,   cudaFuncAttributeMaxDynamicSharedMemorySize, SMEMH_SZ);
    cudaFuncSetAttribute(k_scores, cudaFuncAttributeMaxDynamicSharedMemorySize, SMEMS_SZ);
    cudaFuncSetAttribute(k_pv,     cudaFuncAttributeMaxDynamicSharedMemorySize, SMEMPV_SZ);

    k_prep_x <<<8192, 256>>>(x1, x2);
    k_prep_w <<<dim3(8, 8, 3), dim3(32, 8)>>>(Wq, Wk, Wv);
    k_proj   <<<dim3(2, 128, 3), 256, SMEMH_SZ>>>(bq, bk, bv);
    k_scores <<<dim3(NCOLB, 32, 4), 256, SMEMS_SZ>>>(msk);
    k_sumL   <<<ROWS / 256, 256>>>();
    k_pv     <<<dim3(1, 32, 4), 512, SMEMPV_SZ>>>(out);
}

// round 15
// speedup vs baseline: 1.0721x; 1.0199x over previous
#include <cuda_runtime.h>
#include <cuda_fp16.h>
#include <cstdint>
#include <cstddef>

#define BATCH 4
#define NSEQ  4096
#define DHID  256
#define ROWS  16384            // BATCH * NSEQ

#define BM 128
#define KC 32                  // K elements per pipeline chunk
#define TILE_BYTES 8192        // 128 rows * 32 fp16 * 2B

// shared tile geometry for proj/scores: BM=128 x BN=64, warp tile 32x32, 3 CTA/SM
#define S_BN 64
#define S_ABYTES 8192
#define S_STAGE (S_ABYTES + 4096)        // 12288
#define PIPE_SZ (2 * S_STAGE)            // 24576

// k_scores adds the mask tile
#define MASK_SMEM_OFF PIPE_SZ
#define MROW_INTS 68                     // 272 B row stride (16B aligned, bank-shifted)
#define SMEMS_SZ (MASK_SMEM_OFF + BM * MROW_INTS * 4)   // 24576 + 34816 = 59392
#define NCOLB (NSEQ / S_BN)              // 64 column blocks

// k_pv (512-thread, full-DHID)
#define PV_STAGE_BYTES 24576             // A 8KB + B 16KB
#define SMEMPV_SZ (2 * PV_STAGE_BYTES)   // 48 KB

// ---------------- device scratch (all fp16 single-plane) --------------------
__device__ __align__(16) __half g_Xf[(size_t)2 * ROWS * DHID];
__device__ __align__(16) __half g_Wtf[3 * DHID * DHID];
__device__ __align__(16) __half g_Qf[(size_t)ROWS * DHID];
__device__ __align__(16) __half g_Kf[(size_t)ROWS * DHID];
__device__ __align__(16) __half g_Vf[(size_t)BATCH * DHID * NSEQ];
__device__ __align__(16) __half g_Pf[(size_t)ROWS * NSEQ];
__device__ __align__(16) float  g_Lpart[(size_t)ROWS * NCOLB];

// ---------------- PTX helpers (arch-generic) --------------------------------
__device__ __forceinline__ uint32_t smem_u32(const void* p) {
    uint32_t a;
    asm("{ .reg .u64 t; cvta.to.shared.u64 t, %1; cvt.u32.u64 %0, t; }" : "=r"(a) : "l"(p));
    return a;
}
__device__ __forceinline__ uint32_t sw64(uint32_t b) { return b ^ ((b >> 3) & 0x30); }

__device__ __forceinline__ void cpa16(uint32_t dst, const void* src) {
    asm volatile("cp.async.cg.shared.global [%0], [%1], 16;" :: "r"(dst), "l"(src));
}
__device__ __forceinline__ void cp_commit() { asm volatile("cp.async.commit_group;"); }
template<int N> __device__ __forceinline__ void cp_wait() {
    asm volatile("cp.async.wait_group %0;" :: "n"(N));
}
__device__ __forceinline__ void ldm_x4(uint32_t* d, uint32_t a) {
    asm volatile("ldmatrix.sync.aligned.m8n8.x4.shared.b16 {%0,%1,%2,%3}, [%4];"
                 : "=r"(d[0]), "=r"(d[1]), "=r"(d[2]), "=r"(d[3]) : "r"(a));
}
__device__ __forceinline__ void ldm_x2(uint32_t* d, uint32_t a) {
    asm volatile("ldmatrix.sync.aligned.m8n8.x2.shared.b16 {%0,%1}, [%2];"
                 : "=r"(d[0]), "=r"(d[1]) : "r"(a));
}
__device__ __forceinline__ void mma16816h(float* d, const uint32_t* a, const uint32_t* b) {
    asm volatile("mma.sync.aligned.m16n8k16.row.col.f32.f16.f16.f32 "
                 "{%0,%1,%2,%3}, {%4,%5,%6,%7}, {%8,%9}, {%0,%1,%2,%3};"
                 : "+f"(d[0]), "+f"(d[1]), "+f"(d[2]), "+f"(d[3])
                 : "r"(a[0]), "r"(a[1]), "r"(a[2]), "r"(a[3]), "r"(b[0]), "r"(b[1]));
}

__device__ __forceinline__ uint32_t packh2(float a, float b) {
    __half2 h = __floats2half2_rn(a, b);
    return *(uint32_t*)&h;
}

// exp(x) on FMA pipe (MUFU shares MIO with LSU/ldmatrix: measured +25us there)
__device__ __forceinline__ float fast_exp(float x) {
    float t = x * 1.4426950408889634f;
    float n = floorf(t);
    float f = t - n;
    float p = 1.5404027e-4f;
    p = fmaf(p, f, 1.3333558e-3f);
    p = fmaf(p, f, 9.6181291e-3f);
    p = fmaf(p, f, 5.5504109e-2f);
    p = fmaf(p, f, 2.4022651e-1f);
    p = fmaf(p, f, 6.9314718e-1f);
    p = fmaf(p, f, 1.0f);
    int ni = (int)n;
    ni = max(ni, -126);
    return p * __int_as_float((ni + 127) << 23);
}

// ---------------- 128x64 tile machinery (proj / scores), A,B ld = DHID ------
__device__ __forceinline__ void prefetch_s(const __half* A, const __half* B,
                                           int c, int s, uint32_t sbase, int tid) {
    uint32_t stb = sbase + s * S_STAGE;
    // A: 128 rows x 4 chunks = 512 chunks of 16B
    #pragma unroll
    for (int i = 0; i < 2; ++i) {
        int idx = tid + i * 256;
        int row = idx >> 2, seg = idx & 3;
        uint32_t d = sw64((uint32_t)row * 64 + seg * 16);
        cpa16(stb + d, (const char*)(A + (size_t)row * DHID + (size_t)c * KC) + seg * 16);
    }
    // B: 64 rows x 4 chunks = 256 chunks of 16B
    {
        int row = tid >> 2, seg = tid & 3;
        uint32_t d = sw64((uint32_t)row * 64 + seg * 16);
        cpa16(stb + S_ABYTES + d,
              (const char*)(B + (size_t)row * DHID + (size_t)c * KC) + seg * 16);
    }
    cp_commit();
}

__device__ __forceinline__ void compute_s(uint32_t stb, int wm, int wn, int lane,
                                          float acc[2][4][4]) {
    #pragma unroll
    for (int ks = 0; ks < 2; ++ks) {
        uint32_t a[2][4];
        int am  = (lane & 7) + ((lane >> 3) & 1) * 8;
        int akb = ks * 32 + (lane >> 4) * 16;
        #pragma unroll
        for (int mt = 0; mt < 2; ++mt) {
            uint32_t off = (uint32_t)(wm + mt * 16 + am) * 64 + akb;
            ldm_x4(a[mt], stb + sw64(off));
        }
        uint32_t b[4][2];
        int l16 = lane & 15;
        int bn  = l16 & 7;
        int bkb = ks * 32 + (l16 >> 3) * 16;
        #pragma unroll
        for (int nt = 0; nt < 4; ++nt) {
            uint32_t off = (uint32_t)(wn + nt * 8 + bn) * 64 + bkb;
            ldm_x2(b[nt], stb + S_ABYTES + sw64(off));
        }
        #pragma unroll
        for (int mt = 0; mt < 2; ++mt)
            #pragma unroll
            for (int nt = 0; nt < 4; ++nt)
                mma16816h(acc[mt][nt], a[mt], b[nt]);
    }
}

__device__ __forceinline__ void gemm_s(const __half* A, const __half* B,
                                       char* smem, float acc[2][4][4],
                                       int wm, int wn, int lane, int tid) {
    uint32_t sbase = smem_u32(smem);
    prefetch_s(A, B, 0, 0, sbase, tid);
    const int nchunks = DHID / KC;        // 8
    for (int c = 0; c < nchunks; ++c) {
        int s = c & 1;
        if (c + 1 < nchunks) { prefetch_s(A, B, c + 1, s ^ 1, sbase, tid); cp_wait<1>(); }
        else                 { cp_wait<0>(); }
        __syncthreads();
        compute_s(sbase + s * S_STAGE, wm, wn, lane, acc);
        __syncthreads();
    }
}

// 64x32 warp-tile compute (k_pv only): A plane at stb, B plane at stb+8KB
__device__ __forceinline__ void compute_pv(uint32_t stb, int wm, int wn, int lane,
                                           float acc[4][4][4]) {
    #pragma unroll
    for (int ks = 0; ks < 2; ++ks) {
        uint32_t a[4][4];
        int am  = (lane & 7) + ((lane >> 3) & 1) * 8;
        int akb = ks * 32 + (lane >> 4) * 16;
        #pragma unroll
        for (int mt = 0; mt < 4; ++mt) {
            uint32_t off = (uint32_t)(wm + mt * 16 + am) * 64 + akb;
            ldm_x4(a[mt], stb + sw64(off));
        }
        uint32_t b[4][2];
        int l16 = lane & 15;
        int bn  = l16 & 7;
        int bkb = ks * 32 + (l16 >> 3) * 16;
        #pragma unroll
        for (int nt = 0; nt < 4; ++nt) {
            uint32_t off = (uint32_t)(wn + nt * 8 + bn) * 64 + bkb;
            ldm_x2(b[nt], stb + TILE_BYTES + sw64(off));
        }
        #pragma unroll
        for (int mt = 0; mt < 4; ++mt)
            #pragma unroll
            for (int nt = 0; nt < 4; ++nt)
                mma16816h(acc[mt][nt], a[mt], b[nt]);
    }
}

// ---------------- prep kernels ---------------------------------------------
__global__ __launch_bounds__(256)
void k_prep_x(const float* __restrict__ x1, const float* __restrict__ x2) {
    size_t i = ((size_t)blockIdx.x * 256 + threadIdx.x) * 4;
    const size_t half = (size_t)ROWS * DHID;
    const float* src = (i < half) ? (x1 + i) : (x2 + (i - half));
    float4 v = *(const float4*)src;
    *(uint2*)(g_Xf + i) = make_uint2(packh2(v.x, v.y), packh2(v.z, v.w));
}

__global__ void k_prep_w(const float* __restrict__ Wq, const float* __restrict__ Wk,
                         const float* __restrict__ Wv) {
    __shared__ float t[32][33];
    int z = blockIdx.z;
    const float* W = (z == 0) ? Wq : ((z == 1) ? Wk : Wv);
    int n0 = blockIdx.x * 32, d0 = blockIdx.y * 32;
    int tx = threadIdx.x, ty = threadIdx.y;           // block (32,8)
    #pragma unroll
    for (int i = 0; i < 4; ++i)
        t[ty + i * 8][tx] = W[(size_t)(d0 + ty + i * 8) * DHID + n0 + tx];
    __syncthreads();
    #pragma unroll
    for (int i = 0; i < 4; ++i) {
        float f = t[tx][ty + i * 8];
        size_t o = (size_t)z * DHID * DHID + (size_t)(n0 + ty + i * 8) * DHID + d0 + tx;
        g_Wtf[o] = __float2half(f);
    }
}

// ---------------- projection: BM=128 x BN=64, 3 CTA/SM ----------------------
__global__ __launch_bounds__(256, 3)
void k_proj(const float* __restrict__ bq, const float* __restrict__ bk,
            const float* __restrict__ bv) {
    extern __shared__ char smem[];
    int z = blockIdx.z;
    int rowBase = blockIdx.y * BM, colBase = blockIdx.x * S_BN;
    const __half* A = g_Xf + (((z == 0) ? 0 : (size_t)ROWS) + rowBase) * DHID;
    const __half* B = g_Wtf + (size_t)z * DHID * DHID + (size_t)colBase * DHID;

    float acc[2][4][4];
    #pragma unroll
    for (int a = 0; a < 2; ++a)
        #pragma unroll
        for (int b = 0; b < 4; ++b)
            #pragma unroll
            for (int c = 0; c < 4; ++c) acc[a][b][c] = 0.f;

    int tid = threadIdx.x, lane = tid & 31, warp = tid >> 5;
    int wm = (warp >> 1) * 32, wn = (warp & 1) * 32;
    gemm_s(A, B, smem, acc, wm, wn, lane, tid);

    const float* bias = (z == 0) ? bq : ((z == 1) ? bk : bv);
    int rl = lane >> 2, cl = (lane & 3) * 2;
    #pragma unroll
    for (int mt = 0; mt < 2; ++mt)
        #pragma unroll
        for (int nt = 0; nt < 4; ++nt) {
            int col = colBase + wn + nt * 8 + cl;
            float b0 = bias[col], b1 = bias[col + 1];
            #pragma unroll
            for (int h = 0; h < 2; ++h) {
                int r = rowBase + wm + mt * 16 + rl + h * 8;
                float v0 = acc[mt][nt][h * 2 + 0] + b0;
                float v1 = acc[mt][nt][h * 2 + 1] + b1;
                if (z < 2) {
                    __half* d = (z == 0) ? g_Qf : g_Kf;
                    *(uint32_t*)&d[(size_t)r * DHID + col] = packh2(v0, v1);
                } else {
                    int bb = r >> 12, j = r & 4095;
                    size_t o0 = ((size_t)(bb * DHID + col)) * NSEQ + j;
                    g_Vf[o0]        = __float2half(v0);
                    g_Vf[o0 + NSEQ] = __float2half(v1);
                }
            }
        }
}

// ---------------- scores: BM=128 x BN=64, warp tile 32x32, 3 CTA/SM ---------
__global__ __launch_bounds__(256, 3)
void k_scores(const int* __restrict__ mask) {
    extern __shared__ char smem[];
    int bz = blockIdx.z;
    int rowBase = blockIdx.y * BM, colBase = blockIdx.x * S_BN;
    const __half* A = g_Qf + ((size_t)bz * NSEQ + rowBase) * DHID;
    const __half* B = g_Kf + ((size_t)bz * NSEQ + colBase) * DHID;
    int tid = threadIdx.x;
    uint32_t sbase = smem_u32(smem);

    // mask tile prefetch: 128 rows x 64 ints, smem row stride 272 B
    {
        const char* msrc = (const char*)(mask
            + ((size_t)bz * NSEQ + rowBase) * NSEQ + colBase);
        uint32_t mdst = sbase + MASK_SMEM_OFF;
        #pragma unroll
        for (int i = 0; i < 8; ++i) {
            int idx = tid + i * 256;          // 16B chunk id, 0..2047
            int row = idx >> 4, seg = idx & 15;
            cpa16(mdst + (uint32_t)(row * (MROW_INTS * 4) + seg * 16),
                  msrc + (size_t)row * NSEQ * 4 + seg * 16);
        }
        cp_commit();
    }

    float acc[2][4][4];
    #pragma unroll
    for (int a = 0; a < 2; ++a)
        #pragma unroll
        for (int b = 0; b < 4; ++b)
            #pragma unroll
            for (int c = 0; c < 4; ++c) acc[a][b][c] = 0.f;

    int lane = tid & 31, warp = tid >> 5;
    int wm = (warp >> 1) * 32, wn = (warp & 1) * 32;
    gemm_s(A, B, smem, acc, wm, wn, lane, tid);
    // final cp_wait<0> + syncthreads guarantees mask residency

    int rl = lane >> 2, cl = (lane & 3) * 2;
    const float scale = 0.0625f;
    const int* msm = (const int*)(smem + MASK_SMEM_OFF);

    float rs[2][2];
    rs[0][0] = rs[0][1] = rs[1][0] = rs[1][1] = 0.f;

    #pragma unroll
    for (int mt = 0; mt < 2; ++mt)
        #pragma unroll
        for (int h = 0; h < 2; ++h) {
            int rL = wm + mt * 16 + rl + h * 8;
            const int* mrow = msm + rL * MROW_INTS + wn + cl;
            __half* prow = g_Pf + ((size_t)bz * NSEQ + rowBase + rL) * NSEQ
                         + colBase + wn + cl;
            #pragma unroll
            for (int nt = 0; nt < 4; ++nt) {
                int2 mk = *(const int2*)(mrow + nt * 8);
                float e0 = (mk.x > 0) ? fast_exp(acc[mt][nt][h * 2 + 0] * scale) : 1.0f;
                float e1 = (mk.y > 0) ? fast_exp(acc[mt][nt][h * 2 + 1] * scale) : 1.0f;
                rs[mt][h] += e0 + e1;
                *(uint32_t*)(prow + nt * 8) = packh2(e0, e1);
            }
        }

    // row-sum reduce: quad lanes (shfl), then the 2 warps sharing each row (smem)
    float* sRed = (float*)smem;                 // [128][2]
    __syncthreads();
    #pragma unroll
    for (int mt = 0; mt < 2; ++mt)
        #pragma unroll
        for (int h = 0; h < 2; ++h) {
            float v = rs[mt][h];
            v += __shfl_xor_sync(~0u, v, 1);
            v += __shfl_xor_sync(~0u, v, 2);
            if ((lane & 3) == 0) {
                int lr = wm + mt * 16 + rl + h * 8;
                sRed[lr * 2 + (warp & 1)] = v;
            }
        }
    __syncthreads();
    if (tid < 128) {
        float s = sRed[tid * 2] + sRed[tid * 2 + 1];
        g_Lpart[((size_t)bz * NSEQ + rowBase + tid) * NCOLB + blockIdx.x] = s;
    }
}

// ---------------- PV: 512 threads, BM=128 x full DHID=256; L reduced inline -
__device__ __forceinline__ void prefetch_pv(const __half* A, const __half* B,
                                            int c, int s, uint32_t sbase, int tid) {
    uint32_t stb = sbase + s * PV_STAGE_BYTES;
    // A: 512 chunks of 16B
    {
        int row = tid >> 2, seg = tid & 3;
        uint32_t d = sw64((uint32_t)row * 64 + seg * 16);
        cpa16(stb + d, (const char*)(A + (size_t)row * NSEQ + (size_t)c * KC) + seg * 16);
    }
    // B: 1024 chunks of 16B
    #pragma unroll
    for (int i = 0; i < 2; ++i) {
        int cidx = tid + i * 512;
        int row = cidx >> 2, seg = cidx & 3;
        uint32_t d = sw64((uint32_t)row * 64 + seg * 16);
        cpa16(stb + TILE_BYTES + d,
              (const char*)(B + (size_t)row * NSEQ + (size_t)c * KC) + seg * 16);
    }
    cp_commit();
}

__global__ __launch_bounds__(512, 1)
void k_pv(float* __restrict__ out) {
    extern __shared__ char smem[];
    int bz = blockIdx.z;
    int rowBase = blockIdx.y * BM;
    const __half* A = g_Pf + ((size_t)bz * NSEQ + rowBase) * NSEQ;
    const __half* B = g_Vf + (size_t)bz * DHID * NSEQ;

    float acc[4][4][4];
    #pragma unroll
    for (int a = 0; a < 4; ++a)
        #pragma unroll
        for (int b = 0; b < 4; ++b)
            #pragma unroll
            for (int c = 0; c < 4; ++c) acc[a][b][c] = 0.f;

    int tid = threadIdx.x, lane = tid & 31, warp = tid >> 5;
    // 16 warps: 2 (M) x 8 (N)
    int wm = (warp >> 3) * 64, wn = (warp & 7) * 32;
    uint32_t sbase = smem_u32(smem);
    prefetch_pv(A, B, 0, 0, sbase, tid);
    const int nchunks = NSEQ / KC;
    for (int c = 0; c < nchunks; ++c) {
        int s = c & 1;
        if (c + 1 < nchunks) { prefetch_pv(A, B, c + 1, s ^ 1, sbase, tid); cp_wait<1>(); }
        else                 { cp_wait<0>(); }
        __syncthreads();
        compute_pv(sbase + s * PV_STAGE_BYTES, wm, wn, lane, acc);
        __syncthreads();
    }

    // inline L reduction: this block owns rows [rowBase, rowBase+128)
    float* lred = (float*)smem;    // [128] (pipeline smem now free)
    if (tid < 128) {
        const float4* p = (const float4*)(g_Lpart
            + ((size_t)bz * NSEQ + rowBase + tid) * NCOLB);
        float s = 0.f;
        #pragma unroll
        for (int i = 0; i < NCOLB / 4; ++i) {
            float4 v = p[i];
            s += (v.x + v.y) + (v.z + v.w);
        }
        lred[tid] = 1.0f / s;
    }
    __syncthreads();

    int rl = lane >> 2, cl = (lane & 3) * 2;
    float linv[4][2];
    #pragma unroll
    for (int mt = 0; mt < 4; ++mt)
        #pragma unroll
        for (int h = 0; h < 2; ++h)
            linv[mt][h] = lred[wm + mt * 16 + rl + h * 8];

    #pragma unroll
    for (int mt = 0; mt < 4; ++mt)
        #pragma unroll
        for (int nt = 0; nt < 4; ++nt) {
            int col = wn + nt * 8 + cl;
            #pragma unroll
            for (int h = 0; h < 2; ++h) {
                int r = rowBase + wm + mt * 16 + rl + h * 8;
                float2 o;
                o.x = acc[mt][nt][h * 2 + 0] * linv[mt][h];
                o.y = acc[mt][nt][h * 2 + 1] * linv[mt][h];
                *(float2*)&out[((size_t)bz * NSEQ + r) * DHID + col] = o;
            }
        }
}

// ---------------------------------------------------------------------------
extern "C" void kernel_launch(void* const* d_in, const int* in_sizes, int n_in,
                              void* d_out, int out_size) {
    const float* x1  = (const float*)d_in[0];
    const float* x2  = (const float*)d_in[1];
    const int*   msk = (const int*)  d_in[2];
    const float* Wq  = (const float*)d_in[3];
    const float* bq  = (const float*)d_in[4];
    const float* Wk  = (const float*)d_in[5];
    const float* bk  = (const float*)d_in[6];
    const float* Wv  = (const float*)d_in[7];
    const float* bv  = (const float*)d_in[8];
    float* out = (float*)d_out;

    cudaFuncSetAttribute(k_proj,   cudaFuncAttributeMaxDynamicSharedMemorySize, PIPE_SZ);
    cudaFuncSetAttribute(k_scores, cudaFuncAttributeMaxDynamicSharedMemorySize, SMEMS_SZ);
    cudaFuncSetAttribute(k_pv,     cudaFuncAttributeMaxDynamicSharedMemorySize, SMEMPV_SZ);

    k_prep_x <<<8192, 256>>>(x1, x2);
    k_prep_w <<<dim3(8, 8, 3), dim3(32, 8)>>>(Wq, Wk, Wv);
    k_proj   <<<dim3(4, 128, 3), 256, PIPE_SZ>>>(bq, bk, bv);
    k_scores <<<dim3(NCOLB, 32, 4), 256, SMEMS_SZ>>>(msk);
    k_pv     <<<dim3(1, 32, 4), 512, SMEMPV_SZ>>>(out);
}